// round 16
// baseline (speedup 1.0000x reference)
#include <cuda_runtime.h>
#include <cuda_bf16.h>
#include <cstdint>

#define BNTOT 828
#define LDIM 96
#define SDIM 96
#define HDIM 8
#define EDIM 64
#define DDIM 64
#define TL   32

// ---- smem byte offsets ----
// Phase-1 staging (bf16, stride 48B rows):
#define QHI 0u          // 8h*32l*48 = 12288
#define QLO 12288u
#define KHI 24576u      // 8h*96s*48 = 36864
#define KLO 61440u      // end 98304
// Phase-3 V (transposed [d][s], stride 48B), aliases dead phase-1 staging:
#define VTHI 0u         // 8h*64d*48 = 24576
#define VTLO 24576u     // end 49152
// P buffer: f32 rows (h*32+l), stride 98 floats (392B). After softmax the same
// rows hold probs as bf16: hi at byte 0..191, lo at 192..383 of each row.
#define P_B  98304u
#define P_F  24576      // float index
#define PST  98
#define GB_F 49664      // after P (98304+100352=198656)
#define SMEM_BYTES 198720

#define SCORES_ELEMS ((size_t)BNTOT*HDIM*LDIM*SDIM)

__device__ __forceinline__ void mma16816(float* c, const uint32_t* a, const uint32_t* b) {
    asm volatile("mma.sync.aligned.m16n8k16.row.col.f32.bf16.bf16.f32 "
        "{%0,%1,%2,%3},{%4,%5,%6,%7},{%8,%9},{%0,%1,%2,%3};"
        : "+f"(c[0]), "+f"(c[1]), "+f"(c[2]), "+f"(c[3])
        : "r"(a[0]), "r"(a[1]), "r"(a[2]), "r"(a[3]), "r"(b[0]), "r"(b[1]));
}
// split two consecutive floats into packed bf16 hi-pair / lo-pair
__device__ __forceinline__ void split2(float x0, float x1, uint32_t& hp, uint32_t& lp) {
    __nv_bfloat16 h0 = __float2bfloat16_rn(x0);
    __nv_bfloat16 h1 = __float2bfloat16_rn(x1);
    __nv_bfloat16 l0 = __float2bfloat16_rn(x0 - __bfloat162float(h0));
    __nv_bfloat16 l1 = __float2bfloat16_rn(x1 - __bfloat162float(h1));
    __nv_bfloat162 H; H.x = h0; H.y = h1;
    __nv_bfloat162 L; L.x = l0; L.y = l1;
    hp = *reinterpret_cast<uint32_t*>(&H);
    lp = *reinterpret_cast<uint32_t*>(&L);
}

__global__ __launch_bounds__(512, 1)
void stadd_kernel(const float* __restrict__ qg,
                  const float* __restrict__ kg,
                  const float* __restrict__ vg,
                  const float* __restrict__ maskg,
                  const float* __restrict__ asg,
                  const float* __restrict__ gammag,
                  const float* __restrict__ betag,
                  float* __restrict__ scores_out,
                  float* __restrict__ vout)
{
    extern __shared__ float sm[];
    char* smc = reinterpret_cast<char*>(sm);

    const int bn   = blockIdx.x / 3;
    const int lt   = blockIdx.x % 3;
    const int l0   = lt * TL;
    const int tid  = threadIdx.x;
    const int warp = tid >> 5;
    const int lane = tid & 31;
    const int h1   = warp >> 1;     // head
    const int half = warp & 1;      // s-half (ph1: 48) / d-half (ph3: 32)
    const int gid  = lane >> 2;     // fragment row group 0..7
    const int tg   = lane & 3;      // fragment k/n sub 0..3

    if (tid < HDIM) { sm[GB_F + tid] = gammag[tid]; sm[GB_F + 8 + tid] = betag[tid]; }

    // ================= PHASE 1: P = Q.K^T  (mma.sync bf16 split, e-chunks of 16)
    {
        float acc[2][6][4];
        #pragma unroll
        for (int mt = 0; mt < 2; mt++)
            #pragma unroll
            for (int nt = 0; nt < 6; nt++)
                #pragma unroll
                for (int r = 0; r < 4; r++) acc[mt][nt][r] = 0.f;

        #pragma unroll 1
        for (int ec = 0; ec < 4; ec++) {
            __syncthreads();     // previous round's reads done
            // --- stage K e-chunk: 8h*96s*4(e4) float4 = 3072 -> 6 per thread
            #pragma unroll
            for (int r = 0; r < 6; r++) {
                const int fidx = tid + r * 512;
                const int hh = fidx / 384;
                const int rem = fidx - hh * 384;
                const int s = rem >> 2, e4 = rem & 3;
                const float4 f = *reinterpret_cast<const float4*>(
                    kg + (((size_t)bn * SDIM + s) * HDIM + hh) * EDIM + ec * 16 + e4 * 4);
                uint32_t h01, l01, h23, l23;
                split2(f.x, f.y, h01, l01);
                split2(f.z, f.w, h23, l23);
                const uint32_t off = (uint32_t)(hh * 4608 + s * 48 + e4 * 8);
                *reinterpret_cast<uint2*>(smc + KHI + off) = make_uint2(h01, h23);
                *reinterpret_cast<uint2*>(smc + KLO + off) = make_uint2(l01, l23);
            }
            // --- stage Q e-chunk: 8h*32l*4 float4 = 1024 -> 2 per thread
            #pragma unroll
            for (int r = 0; r < 2; r++) {
                const int fidx = tid + r * 512;
                const int hh = fidx >> 7;
                const int rem = fidx & 127;
                const int l = rem >> 2, e4 = rem & 3;
                const float4 f = *reinterpret_cast<const float4*>(
                    qg + (((size_t)bn * LDIM + l0 + l) * HDIM + hh) * EDIM + ec * 16 + e4 * 4);
                uint32_t h01, l01, h23, l23;
                split2(f.x, f.y, h01, l01);
                split2(f.z, f.w, h23, l23);
                const uint32_t off = (uint32_t)(hh * 1536 + l * 48 + e4 * 8);
                *reinterpret_cast<uint2*>(smc + QHI + off) = make_uint2(h01, h23);
                *reinterpret_cast<uint2*>(smc + QLO + off) = make_uint2(l01, l23);
            }
            __syncthreads();

            // --- A fragments (hi/lo) for both m-tiles
            uint32_t ahi[2][4], alo[2][4];
            #pragma unroll
            for (int mt = 0; mt < 2; mt++) {
                const uint32_t qo = (uint32_t)(h1 * 1536 + (mt * 16 + gid) * 48 + tg * 4);
                ahi[mt][0] = *reinterpret_cast<uint32_t*>(smc + QHI + qo);
                ahi[mt][1] = *reinterpret_cast<uint32_t*>(smc + QHI + qo + 8 * 48);
                ahi[mt][2] = *reinterpret_cast<uint32_t*>(smc + QHI + qo + 16);
                ahi[mt][3] = *reinterpret_cast<uint32_t*>(smc + QHI + qo + 8 * 48 + 16);
                alo[mt][0] = *reinterpret_cast<uint32_t*>(smc + QLO + qo);
                alo[mt][1] = *reinterpret_cast<uint32_t*>(smc + QLO + qo + 8 * 48);
                alo[mt][2] = *reinterpret_cast<uint32_t*>(smc + QLO + qo + 16);
                alo[mt][3] = *reinterpret_cast<uint32_t*>(smc + QLO + qo + 8 * 48 + 16);
            }
            #pragma unroll
            for (int nt = 0; nt < 6; nt++) {
                const uint32_t ko = (uint32_t)(h1 * 4608 + (half * 48 + nt * 8 + gid) * 48 + tg * 4);
                uint32_t bhi[2], blo[2];
                bhi[0] = *reinterpret_cast<uint32_t*>(smc + KHI + ko);
                bhi[1] = *reinterpret_cast<uint32_t*>(smc + KHI + ko + 16);
                blo[0] = *reinterpret_cast<uint32_t*>(smc + KLO + ko);
                blo[1] = *reinterpret_cast<uint32_t*>(smc + KLO + ko + 16);
                #pragma unroll
                for (int mt = 0; mt < 2; mt++) {
                    mma16816(acc[mt][nt], ahi[mt], bhi);
                    mma16816(acc[mt][nt], ahi[mt], blo);
                    mma16816(acc[mt][nt], alo[mt], bhi);
                }
            }
        }

        // --- store accumulators -> P f32
        #pragma unroll
        for (int mt = 0; mt < 2; mt++) {
            #pragma unroll
            for (int nt = 0; nt < 6; nt++) {
                const int row = h1 * 32 + mt * 16 + gid;
                const int col = half * 48 + nt * 8 + tg * 2;
                float* p = sm + P_F + row * PST + col;
                *reinterpret_cast<float2*>(p) = make_float2(acc[mt][nt][0], acc[mt][nt][1]);
                *reinterpret_cast<float2*>(p + 8 * PST) = make_float2(acc[mt][nt][2], acc[mt][nt][3]);
            }
        }
    }
    __syncthreads();

    // ================= PHASE 2: +mask +attn_scores, LayerNorm over H, write scores
    {
        const size_t as_bn = (size_t)bn * HDIM * LDIM * SDIM;
        #pragma unroll 1
        for (int it = 0; it < 6; it++) {
            const int idx = tid + it * 512;
            const int l = idx / SDIM;
            const int s = idx - l * SDIM;
            const float mk = maskg[(l0 + l) * SDIM + s];
            const size_t base = as_bn + (size_t)(l0 + l) * SDIM + s;
            float x[8];
            float mean = 0.f;
            #pragma unroll
            for (int hh = 0; hh < 8; hh++) {
                float val = sm[P_F + (hh * TL + l) * PST + s] + mk
                          + asg[base + (size_t)hh * LDIM * SDIM];
                x[hh] = val; mean += val;
            }
            mean *= 0.125f;
            float var = 0.f;
            #pragma unroll
            for (int hh = 0; hh < 8; hh++) { float d = x[hh] - mean; var += d * d; }
            var *= 0.125f;
            const float rstd = rsqrtf(var + 1e-5f);
            #pragma unroll
            for (int hh = 0; hh < 8; hh++) {
                float sc = (x[hh] - mean) * rstd * sm[GB_F + hh] + sm[GB_F + 8 + hh];
                scores_out[base + (size_t)hh * LDIM * SDIM] = sc;
                sm[P_F + (hh * TL + l) * PST + s] = sc;
            }
        }
    }
    __syncthreads();

    // ================= Softmax over s (temp=1/8): 256 rows, 16 per warp.
    // Writes probs IN PLACE as bf16: hi at row bytes [0,192), lo at [192,384).
    {
        #pragma unroll 1
        for (int rr = 0; rr < 16; rr++) {
            const int row = warp * 16 + rr;
            float* rf = sm + P_F + row * PST;
            float v0 = rf[lane], v1 = rf[lane + 32], v2 = rf[lane + 64];
            float m = fmaxf(v0, fmaxf(v1, v2));
            #pragma unroll
            for (int off = 16; off > 0; off >>= 1)
                m = fmaxf(m, __shfl_xor_sync(0xffffffffu, m, off));
            float e0 = __expf((v0 - m) * 0.125f);
            float e1 = __expf((v1 - m) * 0.125f);
            float e2 = __expf((v2 - m) * 0.125f);
            float sum = e0 + e1 + e2;
            #pragma unroll
            for (int off = 16; off > 0; off >>= 1)
                sum += __shfl_xor_sync(0xffffffffu, sum, off);
            const float inv = 1.f / sum;
            e0 *= inv; e1 *= inv; e2 *= inv;
            char* rb = smc + P_B + (uint32_t)row * 392u;
            #pragma unroll
            for (int q = 0; q < 3; q++) {
                const float pv = (q == 0) ? e0 : (q == 1) ? e1 : e2;
                const int s = lane + q * 32;
                __nv_bfloat16 hi = __float2bfloat16_rn(pv);
                __nv_bfloat16 lo = __float2bfloat16_rn(pv - __bfloat162float(hi));
                *reinterpret_cast<__nv_bfloat16*>(rb + s * 2) = hi;
                *reinterpret_cast<__nv_bfloat16*>(rb + 192 + s * 2) = lo;
            }
        }
    }

    // ================= PHASE 3: O = A.V  (mma.sync bf16 split, s-chunks of 16)
    {
        float o[2][4][4];
        #pragma unroll
        for (int mt = 0; mt < 2; mt++)
            #pragma unroll
            for (int nt = 0; nt < 4; nt++)
                #pragma unroll
                for (int r = 0; r < 4; r++) o[mt][nt][r] = 0.f;

        #pragma unroll 1
        for (int sc = 0; sc < 6; sc++) {
            __syncthreads();     // prev compute reads done (also orders softmax at sc=0)
            // --- stage V chunk transposed: 8h*16s*16(d4) float4 = 2048 -> 4/thread
            #pragma unroll
            for (int r = 0; r < 4; r++) {
                const int fidx = tid + r * 512;
                const int hh = fidx >> 8;
                const int rem = fidx & 255;
                const int s = rem >> 4, d4 = rem & 15;
                const float4 f = *reinterpret_cast<const float4*>(
                    vg + (((size_t)bn * SDIM + sc * 16 + s) * HDIM + hh) * DDIM + d4 * 4);
                const float fv[4] = {f.x, f.y, f.z, f.w};
                #pragma unroll
                for (int j = 0; j < 4; j++) {
                    const int d = d4 * 4 + j;
                    __nv_bfloat16 hi = __float2bfloat16_rn(fv[j]);
                    __nv_bfloat16 lo = __float2bfloat16_rn(fv[j] - __bfloat162float(hi));
                    const uint32_t off = (uint32_t)(hh * 3072 + d * 48 + s * 2);
                    *reinterpret_cast<__nv_bfloat16*>(smc + VTHI + off) = hi;
                    *reinterpret_cast<__nv_bfloat16*>(smc + VTLO + off) = lo;
                }
            }
            __syncthreads();

            // --- A fragments from P-bf16 (hi/lo), k = sc*16 + ...
            uint32_t ahi[2][4], alo[2][4];
            #pragma unroll
            for (int mt = 0; mt < 2; mt++) {
                const uint32_t ao = P_B + (uint32_t)((h1 * 32 + mt * 16 + gid) * 392)
                                  + (uint32_t)(sc * 32 + tg * 4);
                ahi[mt][0] = *reinterpret_cast<uint32_t*>(smc + ao);
                ahi[mt][1] = *reinterpret_cast<uint32_t*>(smc + ao + 8 * 392);
                ahi[mt][2] = *reinterpret_cast<uint32_t*>(smc + ao + 16);
                ahi[mt][3] = *reinterpret_cast<uint32_t*>(smc + ao + 8 * 392 + 16);
                alo[mt][0] = *reinterpret_cast<uint32_t*>(smc + ao + 192);
                alo[mt][1] = *reinterpret_cast<uint32_t*>(smc + ao + 192 + 8 * 392);
                alo[mt][2] = *reinterpret_cast<uint32_t*>(smc + ao + 192 + 16);
                alo[mt][3] = *reinterpret_cast<uint32_t*>(smc + ao + 192 + 8 * 392 + 16);
            }
            #pragma unroll
            for (int nt = 0; nt < 4; nt++) {
                const uint32_t vo = (uint32_t)(h1 * 3072 + (half * 32 + nt * 8 + gid) * 48 + tg * 4);
                uint32_t bhi[2], blo[2];
                bhi[0] = *reinterpret_cast<uint32_t*>(smc + VTHI + vo);
                bhi[1] = *reinterpret_cast<uint32_t*>(smc + VTHI + vo + 16);
                blo[0] = *reinterpret_cast<uint32_t*>(smc + VTLO + vo);
                blo[1] = *reinterpret_cast<uint32_t*>(smc + VTLO + vo + 16);
                #pragma unroll
                for (int mt = 0; mt < 2; mt++) {
                    mma16816(o[mt][nt], ahi[mt], bhi);
                    mma16816(o[mt][nt], ahi[mt], blo);
                    mma16816(o[mt][nt], alo[mt], bhi);
                }
            }
        }

        // --- epilogue: accumulators -> vout [bn][l][h][d]
        #pragma unroll
        for (int mt = 0; mt < 2; mt++) {
            #pragma unroll
            for (int nt = 0; nt < 4; nt++) {
                const int l = mt * 16 + gid;
                const int d = half * 32 + nt * 8 + tg * 2;
                float* g = vout + (((size_t)bn * LDIM + l0 + l) * HDIM + h1) * DDIM + d;
                *reinterpret_cast<float2*>(g) = make_float2(o[mt][nt][0], o[mt][nt][1]);
                *reinterpret_cast<float2*>(g + 8 * HDIM * DDIM)
                    = make_float2(o[mt][nt][2], o[mt][nt][3]);
            }
        }
    }
}

extern "C" void kernel_launch(void* const* d_in, const int* in_sizes, int n_in,
                              void* d_out, int out_size) {
    const float* q     = (const float*)d_in[0];
    const float* k     = (const float*)d_in[1];
    const float* v     = (const float*)d_in[2];
    const float* mask  = (const float*)d_in[3];
    const float* ascr  = (const float*)d_in[4];
    const float* gamma = (const float*)d_in[5];
    const float* beta  = (const float*)d_in[6];

    float* scores = (float*)d_out;
    float* vo     = scores + SCORES_ELEMS;

    cudaFuncSetAttribute(stadd_kernel,
                         cudaFuncAttributeMaxDynamicSharedMemorySize, SMEM_BYTES);
    stadd_kernel<<<BNTOT * 3, 512, SMEM_BYTES>>>(q, k, v, mask, ascr, gamma, beta,
                                                 scores, vo);
}

// round 17
// speedup vs baseline: 1.3652x; 1.3652x over previous
#include <cuda_runtime.h>
#include <cuda_bf16.h>
#include <cstdint>

#define BNTOT 828
#define LDIM 96
#define SDIM 96
#define HDIM 8
#define EDIM 64
#define DDIM 64
#define TL   32

// ---- smem byte offsets ----
#define QHI 0u          // 8h*32l*48 = 12288
#define QLO 12288u
#define KHI 24576u      // 8h*96s*48 = 36864
#define KLO 61440u      // end 98304
// phase-2 prefetch buffers (alias dead K region):
#define ASG_B  24576u   // 2 x 8h x 4096B = 65536 -> ends 90112
#define MASK_B 90112u   // 2 x 4096B -> ends 98304
// phase-3 V transposed [h][d][s-pair], stride 52B (aliases dead Q + ASG buf0):
#define VTHI 0u         // 8h*64d*52 = 26624
#define VTLO 26624u     // end 53248
// P buffer: f32 rows (h*32+l), stride 98 floats. After softmax rows hold bf16
// probs: hi bytes [0,192), lo [192,384) of each 392B row.
#define P_B  98304u
#define P_F  24576
#define PST  98
#define GB_F 49664
#define SMEM_BYTES 198720

#define SCORES_ELEMS ((size_t)BNTOT*HDIM*LDIM*SDIM)

__device__ __forceinline__ void mma16816(float* c, const uint32_t* a, const uint32_t* b) {
    asm volatile("mma.sync.aligned.m16n8k16.row.col.f32.bf16.bf16.f32 "
        "{%0,%1,%2,%3},{%4,%5,%6,%7},{%8,%9},{%0,%1,%2,%3};"
        : "+f"(c[0]), "+f"(c[1]), "+f"(c[2]), "+f"(c[3])
        : "r"(a[0]), "r"(a[1]), "r"(a[2]), "r"(a[3]), "r"(b[0]), "r"(b[1]));
}
__device__ __forceinline__ void split2(float x0, float x1, uint32_t& hp, uint32_t& lp) {
    __nv_bfloat16 h0 = __float2bfloat16_rn(x0);
    __nv_bfloat16 h1 = __float2bfloat16_rn(x1);
    __nv_bfloat16 l0 = __float2bfloat16_rn(x0 - __bfloat162float(h0));
    __nv_bfloat16 l1 = __float2bfloat16_rn(x1 - __bfloat162float(h1));
    __nv_bfloat162 H; H.x = h0; H.y = h1;
    __nv_bfloat162 L; L.x = l0; L.y = l1;
    hp = *reinterpret_cast<uint32_t*>(&H);
    lp = *reinterpret_cast<uint32_t*>(&L);
}
__device__ __forceinline__ uint32_t pack_hi(float x0, float x1) {
    __nv_bfloat162 H; H.x = __float2bfloat16_rn(x0); H.y = __float2bfloat16_rn(x1);
    return *reinterpret_cast<uint32_t*>(&H);
}
__device__ __forceinline__ uint32_t pack_lo(float x0, float x1) {
    __nv_bfloat16 h0 = __float2bfloat16_rn(x0);
    __nv_bfloat16 h1 = __float2bfloat16_rn(x1);
    __nv_bfloat162 L;
    L.x = __float2bfloat16_rn(x0 - __bfloat162float(h0));
    L.y = __float2bfloat16_rn(x1 - __bfloat162float(h1));
    return *reinterpret_cast<uint32_t*>(&L);
}
__device__ __forceinline__ void cp16(uint32_t dst, const float* src) {
    asm volatile("cp.async.ca.shared.global [%0], [%1], 16;" :: "r"(dst), "l"(src));
}
__device__ __forceinline__ void cp_commit() {
    asm volatile("cp.async.commit_group;" ::: "memory");
}
template <int N> __device__ __forceinline__ void cp_wait() {
    asm volatile("cp.async.wait_group %0;" :: "n"(N) : "memory");
}

__global__ __launch_bounds__(1024, 1)
void stadd_kernel(const float* __restrict__ qg,
                  const float* __restrict__ kg,
                  const float* __restrict__ vg,
                  const float* __restrict__ maskg,
                  const float* __restrict__ asg,
                  const float* __restrict__ gammag,
                  const float* __restrict__ betag,
                  float* __restrict__ scores_out,
                  float* __restrict__ vout)
{
    extern __shared__ float sm[];
    char* smc = reinterpret_cast<char*>(sm);
    uint32_t smb;
    asm("{ .reg .u64 t; cvta.to.shared.u64 t, %1; cvt.u32.u64 %0, t; }"
        : "=r"(smb) : "l"(sm));

    const int bn   = blockIdx.x / 3;
    const int lt   = blockIdx.x % 3;
    const int l0   = lt * TL;
    const int tid  = threadIdx.x;
    const int warp = tid >> 5;
    const int lane = tid & 31;
    const int h1   = warp >> 2;     // head
    const int quad = warp & 3;      // s-quarter (ph1: 24) / d-quarter (ph3: 16)
    const int gid  = lane >> 2;     // fragment row group 0..7
    const int tg   = lane & 3;      // fragment k/n sub 0..3

    if (tid < HDIM) { sm[GB_F + tid] = gammag[tid]; sm[GB_F + 8 + tid] = betag[tid]; }

    // ================= PHASE 1: P = Q.K^T (mma.sync bf16 split, e-chunks of 16)
    {
        float acc[2][3][4];
        #pragma unroll
        for (int mt = 0; mt < 2; mt++)
            #pragma unroll
            for (int nt = 0; nt < 3; nt++)
                #pragma unroll
                for (int r = 0; r < 4; r++) acc[mt][nt][r] = 0.f;

        #pragma unroll 1
        for (int ec = 0; ec < 4; ec++) {
            __syncthreads();
            // --- stage K e-chunk: 8h*96s*4(e4) float4 = 3072 -> 3 per thread
            #pragma unroll
            for (int r = 0; r < 3; r++) {
                const int fidx = tid + r * 1024;
                const int hh = fidx / 384;
                const int rem = fidx - hh * 384;
                const int s = rem >> 2, e4 = rem & 3;
                const float4 f = *reinterpret_cast<const float4*>(
                    kg + (((size_t)bn * SDIM + s) * HDIM + hh) * EDIM + ec * 16 + e4 * 4);
                uint32_t h01, l01, h23, l23;
                split2(f.x, f.y, h01, l01);
                split2(f.z, f.w, h23, l23);
                const uint32_t off = (uint32_t)(hh * 4608 + s * 48 + e4 * 8);
                *reinterpret_cast<uint2*>(smc + KHI + off) = make_uint2(h01, h23);
                *reinterpret_cast<uint2*>(smc + KLO + off) = make_uint2(l01, l23);
            }
            // --- stage Q e-chunk: 8h*32l*4 float4 = 1024 -> 1 per thread
            {
                const int hh = tid >> 7;
                const int rem = tid & 127;
                const int l = rem >> 2, e4 = rem & 3;
                const float4 f = *reinterpret_cast<const float4*>(
                    qg + (((size_t)bn * LDIM + l0 + l) * HDIM + hh) * EDIM + ec * 16 + e4 * 4);
                uint32_t h01, l01, h23, l23;
                split2(f.x, f.y, h01, l01);
                split2(f.z, f.w, h23, l23);
                const uint32_t off = (uint32_t)(hh * 1536 + l * 48 + e4 * 8);
                *reinterpret_cast<uint2*>(smc + QHI + off) = make_uint2(h01, h23);
                *reinterpret_cast<uint2*>(smc + QLO + off) = make_uint2(l01, l23);
            }
            __syncthreads();

            uint32_t ahi[2][4], alo[2][4];
            #pragma unroll
            for (int mt = 0; mt < 2; mt++) {
                const uint32_t qo = (uint32_t)(h1 * 1536 + (mt * 16 + gid) * 48 + tg * 4);
                ahi[mt][0] = *reinterpret_cast<uint32_t*>(smc + QHI + qo);
                ahi[mt][1] = *reinterpret_cast<uint32_t*>(smc + QHI + qo + 8 * 48);
                ahi[mt][2] = *reinterpret_cast<uint32_t*>(smc + QHI + qo + 16);
                ahi[mt][3] = *reinterpret_cast<uint32_t*>(smc + QHI + qo + 8 * 48 + 16);
                alo[mt][0] = *reinterpret_cast<uint32_t*>(smc + QLO + qo);
                alo[mt][1] = *reinterpret_cast<uint32_t*>(smc + QLO + qo + 8 * 48);
                alo[mt][2] = *reinterpret_cast<uint32_t*>(smc + QLO + qo + 16);
                alo[mt][3] = *reinterpret_cast<uint32_t*>(smc + QLO + qo + 8 * 48 + 16);
            }
            #pragma unroll
            for (int nt = 0; nt < 3; nt++) {
                const uint32_t ko = (uint32_t)(h1 * 4608 + (quad * 24 + nt * 8 + gid) * 48 + tg * 4);
                uint32_t bhi[2], blo[2];
                bhi[0] = *reinterpret_cast<uint32_t*>(smc + KHI + ko);
                bhi[1] = *reinterpret_cast<uint32_t*>(smc + KHI + ko + 16);
                blo[0] = *reinterpret_cast<uint32_t*>(smc + KLO + ko);
                blo[1] = *reinterpret_cast<uint32_t*>(smc + KLO + ko + 16);
                #pragma unroll
                for (int mt = 0; mt < 2; mt++) {
                    mma16816(acc[mt][nt], ahi[mt], bhi);
                    mma16816(acc[mt][nt], ahi[mt], blo);
                    mma16816(acc[mt][nt], alo[mt], bhi);
                }
            }
        }

        #pragma unroll
        for (int mt = 0; mt < 2; mt++) {
            #pragma unroll
            for (int nt = 0; nt < 3; nt++) {
                const int row = h1 * 32 + mt * 16 + gid;
                const int col = quad * 24 + nt * 8 + tg * 2;
                float* p = sm + P_F + row * PST + col;
                *reinterpret_cast<float2*>(p) = make_float2(acc[mt][nt][0], acc[mt][nt][1]);
                *reinterpret_cast<float2*>(p + 8 * PST) = make_float2(acc[mt][nt][2], acc[mt][nt][3]);
            }
        }
    }
    __syncthreads();    // P done; K/Q staging region dead

    // ---- phase-2 prefetch (asg + mask) into dead K region
    const size_t as_bn = (size_t)bn * HDIM * LDIM * SDIM;
    auto pf2 = [&](int it, int b) {
        #pragma unroll
        for (int r = 0; r < 2; r++) {
            const int fidx = tid + r * 1024;
            const int hh = fidx >> 8, j16 = fidx & 255;
            cp16(smb + ASG_B + (uint32_t)(b * 32768 + hh * 4096 + j16 * 16),
                 asg + as_bn + (size_t)hh * LDIM * SDIM + l0 * SDIM + it * 1024 + j16 * 4);
        }
        if (tid < 256)
            cp16(smb + MASK_B + (uint32_t)(b * 4096 + tid * 16),
                 maskg + l0 * SDIM + it * 1024 + tid * 4);
        cp_commit();
    };
    pf2(0, 0);
    pf2(1, 1);

    // ================= PHASE 2: +mask +attn_scores, LayerNorm over H, write scores
    #pragma unroll 1
    for (int it = 0; it < 3; it++) {
        if (it < 2) cp_wait<1>(); else cp_wait<0>();
        __syncthreads();
        const int b = it & 1;
        const int idx = tid + it * 1024;
        const int l = idx / SDIM;
        const int s = idx - l * SDIM;
        const float mk = *reinterpret_cast<const float*>(smc + MASK_B + (uint32_t)(b * 4096 + tid * 4));
        const size_t gbase = as_bn + (size_t)(l0 + l) * SDIM + s;

        float x[8];
        float mean = 0.f;
        #pragma unroll
        for (int hh = 0; hh < 8; hh++) {
            float val = sm[P_F + (hh * TL + l) * PST + s] + mk
                      + *reinterpret_cast<const float*>(
                            smc + ASG_B + (uint32_t)(b * 32768 + hh * 4096 + tid * 4));
            x[hh] = val; mean += val;
        }
        mean *= 0.125f;
        float var = 0.f;
        #pragma unroll
        for (int hh = 0; hh < 8; hh++) { float d = x[hh] - mean; var += d * d; }
        var *= 0.125f;
        const float rstd = rsqrtf(var + 1e-5f);
        #pragma unroll
        for (int hh = 0; hh < 8; hh++) {
            float sc = (x[hh] - mean) * rstd * sm[GB_F + hh] + sm[GB_F + 8 + hh];
            scores_out[gbase + (size_t)hh * LDIM * SDIM] = sc;
            sm[P_F + (hh * TL + l) * PST + s] = sc;
        }
        if (it == 0) { __syncthreads(); pf2(2, 0); }   // buf0 reads done by all
    }
    __syncthreads();

    // ================= Softmax over s (temp=1/8): 256 rows, 8 per warp.
    // In-place bf16 probs: hi at row bytes [0,192), lo at [192,384).
    {
        #pragma unroll 1
        for (int rr = 0; rr < 8; rr++) {
            const int row = warp * 8 + rr;
            float* rf = sm + P_F + row * PST;
            float v0 = rf[lane], v1 = rf[lane + 32], v2 = rf[lane + 64];
            float m = fmaxf(v0, fmaxf(v1, v2));
            #pragma unroll
            for (int off = 16; off > 0; off >>= 1)
                m = fmaxf(m, __shfl_xor_sync(0xffffffffu, m, off));
            float e0 = __expf((v0 - m) * 0.125f);
            float e1 = __expf((v1 - m) * 0.125f);
            float e2 = __expf((v2 - m) * 0.125f);
            float sum = e0 + e1 + e2;
            #pragma unroll
            for (int off = 16; off > 0; off >>= 1)
                sum += __shfl_xor_sync(0xffffffffu, sum, off);
            const float inv = 1.f / sum;
            e0 *= inv; e1 *= inv; e2 *= inv;
            char* rb = smc + P_B + (uint32_t)row * 392u;
            #pragma unroll
            for (int q = 0; q < 3; q++) {
                const float pv = (q == 0) ? e0 : (q == 1) ? e1 : e2;
                const int s = lane + q * 32;
                __nv_bfloat16 hi = __float2bfloat16_rn(pv);
                __nv_bfloat16 lo = __float2bfloat16_rn(pv - __bfloat162float(hi));
                *reinterpret_cast<__nv_bfloat16*>(rb + s * 2) = hi;
                *reinterpret_cast<__nv_bfloat16*>(rb + 192 + s * 2) = lo;
            }
        }
    }

    // ================= PHASE 3: O = A.V (mma.sync bf16 split, s-chunks of 16)
    {
        float o[2][2][4];
        #pragma unroll
        for (int mt = 0; mt < 2; mt++)
            #pragma unroll
            for (int nt = 0; nt < 2; nt++)
                #pragma unroll
                for (int r = 0; r < 4; r++) o[mt][nt][r] = 0.f;

        #pragma unroll 1
        for (int sc = 0; sc < 6; sc++) {
            __syncthreads();   // prev reads done (sc=0: orders softmax + dead ASG)
            // --- stage V chunk transposed [h][d][s-pair], stride 52B; 1 item/thread
            {
                const int hh = tid >> 7;
                const int rem = tid & 127;
                const int sp = rem >> 4, d4 = rem & 15;
                const float4 f0 = *reinterpret_cast<const float4*>(
                    vg + (((size_t)bn * SDIM + sc * 16 + 2 * sp) * HDIM + hh) * DDIM + d4 * 4);
                const float4 f1 = *reinterpret_cast<const float4*>(
                    vg + (((size_t)bn * SDIM + sc * 16 + 2 * sp + 1) * HDIM + hh) * DDIM + d4 * 4);
                const float a0[4] = {f0.x, f0.y, f0.z, f0.w};
                const float a1[4] = {f1.x, f1.y, f1.z, f1.w};
                #pragma unroll
                for (int j = 0; j < 4; j++) {
                    const int d = d4 * 4 + j;
                    const uint32_t off = (uint32_t)(hh * 3328 + d * 52 + sp * 4);
                    *reinterpret_cast<uint32_t*>(smc + VTHI + off) = pack_hi(a0[j], a1[j]);
                    *reinterpret_cast<uint32_t*>(smc + VTLO + off) = pack_lo(a0[j], a1[j]);
                }
            }
            __syncthreads();

            uint32_t ahi[2][4], alo[2][4];
            #pragma unroll
            for (int mt = 0; mt < 2; mt++) {
                const uint32_t ao = P_B + (uint32_t)((h1 * 32 + mt * 16 + gid) * 392)
                                  + (uint32_t)(sc * 32 + tg * 4);
                ahi[mt][0] = *reinterpret_cast<uint32_t*>(smc + ao);
                ahi[mt][1] = *reinterpret_cast<uint32_t*>(smc + ao + 8 * 392);
                ahi[mt][2] = *reinterpret_cast<uint32_t*>(smc + ao + 16);
                ahi[mt][3] = *reinterpret_cast<uint32_t*>(smc + ao + 8 * 392 + 16);
                alo[mt][0] = *reinterpret_cast<uint32_t*>(smc + ao + 192);
                alo[mt][1] = *reinterpret_cast<uint32_t*>(smc + ao + 192 + 8 * 392);
                alo[mt][2] = *reinterpret_cast<uint32_t*>(smc + ao + 192 + 16);
                alo[mt][3] = *reinterpret_cast<uint32_t*>(smc + ao + 192 + 8 * 392 + 16);
            }
            #pragma unroll
            for (int nt = 0; nt < 2; nt++) {
                const uint32_t vo = (uint32_t)(h1 * 3328 + (quad * 16 + nt * 8 + gid) * 52 + tg * 4);
                uint32_t bhi[2], blo[2];
                bhi[0] = *reinterpret_cast<uint32_t*>(smc + VTHI + vo);
                bhi[1] = *reinterpret_cast<uint32_t*>(smc + VTHI + vo + 16);
                blo[0] = *reinterpret_cast<uint32_t*>(smc + VTLO + vo);
                blo[1] = *reinterpret_cast<uint32_t*>(smc + VTLO + vo + 16);
                #pragma unroll
                for (int mt = 0; mt < 2; mt++) {
                    mma16816(o[mt][nt], ahi[mt], bhi);
                    mma16816(o[mt][nt], ahi[mt], blo);
                    mma16816(o[mt][nt], alo[mt], bhi);
                }
            }
        }

        #pragma unroll
        for (int mt = 0; mt < 2; mt++) {
            #pragma unroll
            for (int nt = 0; nt < 2; nt++) {
                const int l = mt * 16 + gid;
                const int d = quad * 16 + nt * 8 + tg * 2;
                float* g = vout + (((size_t)bn * LDIM + l0 + l) * HDIM + h1) * DDIM + d;
                *reinterpret_cast<float2*>(g) = make_float2(o[mt][nt][0], o[mt][nt][1]);
                *reinterpret_cast<float2*>(g + 8 * HDIM * DDIM)
                    = make_float2(o[mt][nt][2], o[mt][nt][3]);
            }
        }
    }
}

extern "C" void kernel_launch(void* const* d_in, const int* in_sizes, int n_in,
                              void* d_out, int out_size) {
    const float* q     = (const float*)d_in[0];
    const float* k     = (const float*)d_in[1];
    const float* v     = (const float*)d_in[2];
    const float* mask  = (const float*)d_in[3];
    const float* ascr  = (const float*)d_in[4];
    const float* gamma = (const float*)d_in[5];
    const float* beta  = (const float*)d_in[6];

    float* scores = (float*)d_out;
    float* vo     = scores + SCORES_ELEMS;

    cudaFuncSetAttribute(stadd_kernel,
                         cudaFuncAttributeMaxDynamicSharedMemorySize, SMEM_BYTES);
    stadd_kernel<<<BNTOT * 3, 1024, SMEM_BYTES>>>(q, k, v, mask, ascr, gamma, beta,
                                                  scores, vo);
}